// round 13
// baseline (speedup 1.0000x reference)
#include <cuda_runtime.h>
#include <cuda_fp16.h>
#include <math.h>
#include <stdint.h>

#define MTOK 32768
#define DD   1152
#define HH   4608

typedef __half f16;

// ---------------- scratch (static device globals; no runtime alloc) ----------------
__device__ f16   g_qx[(size_t)MTOK * DD];        // quantized x as fp16 ints (exact)
__device__ float g_xscale[MTOK];
__device__ f16   g_qh[(size_t)MTOK * HH];        // quantized h as fp16 ints (exact)
__device__ float g_hscale[MTOK];
__device__ float g_h[(size_t)MTOK * HH];         // post-GELU h (fp32)
__device__ f16   g_w1p[(size_t)2 * HH * DD];     // W1: plane0 = lo*2048, plane1 = hi
__device__ f16   g_w2p[(size_t)DD * HH];         // W2: single fp16 plane

// ---------------- helpers ----------------
__device__ __forceinline__ float gelu_exact(float v) {
    return 0.5f * v * (1.0f + erff(v * 0.70710678118654752440f));
}
__device__ __forceinline__ void cpa16(void* s, const void* g) {
    unsigned sa = (unsigned)__cvta_generic_to_shared(s);
    asm volatile("cp.async.cg.shared.global [%0], [%1], 16;\n" :: "r"(sa), "l"(g));
}
__device__ __forceinline__ void cpcommit() { asm volatile("cp.async.commit_group;\n"); }
__device__ __forceinline__ void cpwaitg1() { asm volatile("cp.async.wait_group 1;\n"); }

__device__ __forceinline__ void ldm_x4(uint32_t* r, uint32_t addr) {
    asm volatile("ldmatrix.sync.aligned.m8n8.x4.shared.b16 {%0,%1,%2,%3}, [%4];\n"
                 : "=r"(r[0]), "=r"(r[1]), "=r"(r[2]), "=r"(r[3]) : "r"(addr));
}
__device__ __forceinline__ void mma_f16(float* d, const uint32_t* a, uint32_t b0, uint32_t b1) {
    asm volatile("mma.sync.aligned.m16n8k16.row.col.f32.f16.f16.f32 "
                 "{%0,%1,%2,%3}, {%4,%5,%6,%7}, {%8,%9}, {%0,%1,%2,%3};\n"
                 : "+f"(d[0]), "+f"(d[1]), "+f"(d[2]), "+f"(d[3])
                 : "r"(a[0]), "r"(a[1]), "r"(a[2]), "r"(a[3]),
                   "r"(b0), "r"(b1));
}

// ---------------- weight prep ----------------
__global__ void prep_w(const float* __restrict__ W1, const float* __restrict__ W2,
                       f16* __restrict__ w1p, f16* __restrict__ w2p) {
    size_t i = (size_t)blockIdx.x * 256 + threadIdx.x;
    if (i < (size_t)HH * DD) {
        float w = W1[i];
        f16 hi = __float2half_rn(w);
        float lo = w - __half2float(hi);
        w1p[i]                    = __float2half_rn(lo * 2048.0f);
        w1p[(size_t)HH * DD + i]  = hi;
        w2p[i] = __float2half_rn(W2[i]);
    }
}

// ---------------- quant of x (with channel reorder) -> fp16 ints ----------------
__global__ void quant_x_kernel(const float* __restrict__ x, const int* __restrict__ ridx,
                               f16* __restrict__ qx, float* __restrict__ xs) {
    __shared__ float sv[DD];
    __shared__ float red[9];
    int m = blockIdx.x, tid = threadIdx.x;
    const float* row = x + (size_t)m * DD;
    float mx = 0.0f;
    for (int d = tid; d < DD; d += 256) {
        float v = row[ridx[d]];
        sv[d] = v;
        mx = fmaxf(mx, fabsf(v));
    }
    #pragma unroll
    for (int o = 16; o > 0; o >>= 1) mx = fmaxf(mx, __shfl_xor_sync(0xffffffffu, mx, o));
    if ((tid & 31) == 0) red[tid >> 5] = mx;
    __syncthreads();
    if (tid == 0) {
        float t = red[0];
        #pragma unroll
        for (int i = 1; i < 8; i++) t = fmaxf(t, red[i]);
        red[8] = fmaxf(__fdiv_rn(t, 127.0f), 1e-8f);
    }
    __syncthreads();
    float scale = red[8];
    for (int d = tid; d < DD; d += 256) {
        float q = rintf(__fdiv_rn(sv[d], scale));
        q = fminf(fmaxf(q, -128.0f), 127.0f);
        qx[(size_t)m * DD + d] = __float2half_rn(q);   // exact: |q| <= 128
    }
    if (tid == 0) xs[m] = scale;
}

// ---------------- quant of h -> fp16 ints (vectorized, single gmem pass) ----------------
__global__ void quant_h_kernel(const float* __restrict__ h, f16* __restrict__ qh,
                               float* __restrict__ hs) {
    __shared__ float red[9];
    int m = blockIdx.x, tid = threadIdx.x;
    const float4* row = (const float4*)(h + (size_t)m * HH);   // 1152 float4
    float4 v[5];
    float mx = 0.0f;
    #pragma unroll
    for (int i = 0; i < 5; i++) {
        int idx = tid + i * 256;
        if (idx < 1152) {
            v[i] = row[idx];
            mx = fmaxf(mx, fmaxf(fmaxf(fabsf(v[i].x), fabsf(v[i].y)),
                                 fmaxf(fabsf(v[i].z), fabsf(v[i].w))));
        }
    }
    #pragma unroll
    for (int o = 16; o > 0; o >>= 1) mx = fmaxf(mx, __shfl_xor_sync(0xffffffffu, mx, o));
    if ((tid & 31) == 0) red[tid >> 5] = mx;
    __syncthreads();
    if (tid == 0) {
        float t = red[0];
        #pragma unroll
        for (int i = 1; i < 8; i++) t = fmaxf(t, red[i]);
        red[8] = fmaxf(__fdiv_rn(t, 127.0f), 1e-8f);
    }
    __syncthreads();
    float scale = red[8];
    uint2* out = (uint2*)(qh + (size_t)m * HH);   // 4 halves per store
    #pragma unroll
    for (int i = 0; i < 5; i++) {
        int idx = tid + i * 256;
        if (idx < 1152) {
            float q0 = fminf(fmaxf(rintf(__fdiv_rn(v[i].x, scale)), -128.0f), 127.0f);
            float q1 = fminf(fmaxf(rintf(__fdiv_rn(v[i].y, scale)), -128.0f), 127.0f);
            float q2 = fminf(fmaxf(rintf(__fdiv_rn(v[i].z, scale)), -128.0f), 127.0f);
            float q3 = fminf(fmaxf(rintf(__fdiv_rn(v[i].w, scale)), -128.0f), 127.0f);
            __half2 lo = __floats2half2_rn(q0, q1);
            __half2 hi = __floats2half2_rn(q2, q3);
            uint2 pk;
            pk.x = *(uint32_t*)&lo;
            pk.y = *(uint32_t*)&hi;
            out[idx] = pk;
        }
    }
    if (tid == 0) hs[m] = scale;
}

// ---------------- fp16 multi-plane GEMM (mma m16n8k16, ldmatrix, 3-stage pipe) ----------------
// C = op( rs[m] * HornerFold_p(A @ Bp^T) + bias[n] ),  fold scale = psc between planes.
// CTA 128x128, 4 warps (2x2 warp grid), warp tile 64x64. K-chunk = 64 halves.
// Square warp tile cuts smem fragment-read duplication from A*2+B*4 to A*2+B*2
// (96KB -> 64KB reads per chunk per CTA) to relieve the smem crossbar.
// Same R6-proven pipeline: wait -> sync -> compute(st) -> load(st+2); 2 CTAs/SM.
#define KC    64
#define SSTB  144
#define STG   (128 * SSTB)     // 18432 B per stage
#define NSTG  3

template<int P, bool DO_GELU>
__global__ __launch_bounds__(128, 2)
void gemm_f16k(const f16* __restrict__ A, const f16* __restrict__ Bp, float psc,
               const float* __restrict__ rs, const float* __restrict__ bias,
               float* __restrict__ C, int M, int N, int K) {
    extern __shared__ char sm[];
    char* smA = sm;
    char* smB = sm + NSTG * STG;

    const int tid  = threadIdx.x;
    const int m0   = blockIdx.y * 128;
    const int n0   = blockIdx.x * 128;
    const int lane = tid & 31, warp = tid >> 5;
    const int wm = warp >> 1, wn = warp & 1;       // 2 x 2 warp grid, tile 64x64
    const int g  = lane >> 2, t4 = lane & 3;

    float acc[4][8][4];
    #pragma unroll
    for (int mt = 0; mt < 4; mt++)
        #pragma unroll
        for (int nt = 0; nt < 8; nt++)
            #pragma unroll
            for (int i = 0; i < 4; i++) acc[mt][nt][i] = 0.0f;

    const char* Ag = (const char*)(A + (size_t)m0 * K);
    const int cpk = K / KC;
    const int nch = P * cpk;

    // per-lane LDSM byte offsets within a stage
    const int aoffs = (wm * 64 + (lane & 15)) * SSTB + ((lane >> 4) & 1) * 16;
    const int boffs = (wn * 64 + (lane & 7) + ((lane >> 4) & 1) * 8) * SSTB
                    + ((lane >> 3) & 1) * 16;

    auto load_chunk = [&](int ch, int st) {
        int p  = (P == 1) ? 0 : (ch / cpk);
        int kb = ((P == 1) ? ch : (ch % cpk)) * (KC * 2);   // byte offset along K
        const char* Ab = Ag + kb;
        const char* Bb = (const char*)(Bp + (size_t)p * N * K + (size_t)n0 * K) + kb;
        #pragma unroll
        for (int i = 0; i < 8; i++) {
            int id = tid + i * 128;           // 0..1023
            int r = id >> 3, c = (id & 7) << 4;
            cpa16(smA + st * STG + r * SSTB + c, Ab + (size_t)r * (K * 2) + c);
            cpa16(smB + st * STG + r * SSTB + c, Bb + (size_t)r * (K * 2) + c);
        }
    };

    auto compute_stage = [&](int st) {
        uint32_t Abase = (uint32_t)__cvta_generic_to_shared(smA + st * STG) + aoffs;
        uint32_t Bbase = (uint32_t)__cvta_generic_to_shared(smB + st * STG) + boffs;
        #pragma unroll
        for (int ks = 0; ks < 4; ks++) {
            uint32_t a[4][4];
            #pragma unroll
            for (int mtp = 0; mtp < 4; mtp++)
                ldm_x4(a[mtp], Abase + mtp * 16 * SSTB + ks * 32);
            uint32_t bb[4][4];
            #pragma unroll
            for (int ntp = 0; ntp < 4; ntp++)
                ldm_x4(bb[ntp], Bbase + ntp * 16 * SSTB + ks * 32);
            #pragma unroll
            for (int mt = 0; mt < 4; mt++)
                #pragma unroll
                for (int nt = 0; nt < 8; nt++)
                    mma_f16(acc[mt][nt], a[mt], bb[nt >> 1][(nt & 1) * 2],
                            bb[nt >> 1][(nt & 1) * 2 + 1]);
        }
    };

    load_chunk(0, 0); cpcommit();
    load_chunk(1, 1); cpcommit();

    for (int i = 0; i < nch; i++) {
        int st = i % 3;
        cpwaitg1();
        __syncthreads();
        compute_stage(st);
        if (P == 2 && i == cpk - 1) {           // Horner fold between planes
            #pragma unroll
            for (int mt = 0; mt < 4; mt++)
                #pragma unroll
                for (int nt = 0; nt < 8; nt++)
                    #pragma unroll
                    for (int k = 0; k < 4; k++) acc[mt][nt][k] *= psc;
        }
        int j = i + 2;
        if (j < nch) load_chunk(j, j % 3);
        cpcommit();                             // empty group at tail keeps wait semantics
    }

    // epilogue
    #pragma unroll
    for (int mt = 0; mt < 4; mt++) {
        int r0 = m0 + wm * 64 + mt * 16 + g;
        float s0 = rs[r0], s1 = rs[r0 + 8];
        #pragma unroll
        for (int nt = 0; nt < 8; nt++) {
            int c0 = n0 + wn * 64 + nt * 8 + (t4 << 1);
            float bb0 = bias[c0], bb1 = bias[c0 + 1];
            float v00 = acc[mt][nt][0] * s0 + bb0;
            float v01 = acc[mt][nt][1] * s0 + bb1;
            float v10 = acc[mt][nt][2] * s1 + bb0;
            float v11 = acc[mt][nt][3] * s1 + bb1;
            if (DO_GELU) {
                v00 = gelu_exact(v00); v01 = gelu_exact(v01);
                v10 = gelu_exact(v10); v11 = gelu_exact(v11);
            }
            *(float2*)&C[(size_t)r0 * N + c0]       = make_float2(v00, v01);
            *(float2*)&C[(size_t)(r0 + 8) * N + c0] = make_float2(v10, v11);
        }
    }
}

// ---------------- launch ----------------
extern "C" void kernel_launch(void* const* d_in, const int* in_sizes, int n_in,
                              void* d_out, int out_size) {
    const float* x    = (const float*)d_in[0];
    const int*   ridx = (const int*)  d_in[1];
    const float* W1   = (const float*)d_in[2];
    const float* b1   = (const float*)d_in[3];
    const float* W2   = (const float*)d_in[4];
    const float* b2   = (const float*)d_in[5];
    float* out = (float*)d_out;
    (void)in_sizes; (void)n_in; (void)out_size;

    void* p;
    f16 *qx, *qh, *w1p, *w2p;
    float *xs, *hs, *hbuf;
    cudaGetSymbolAddress(&p, g_qx);     qx   = (f16*)p;
    cudaGetSymbolAddress(&p, g_xscale); xs   = (float*)p;
    cudaGetSymbolAddress(&p, g_qh);     qh   = (f16*)p;
    cudaGetSymbolAddress(&p, g_hscale); hs   = (float*)p;
    cudaGetSymbolAddress(&p, g_h);      hbuf = (float*)p;
    cudaGetSymbolAddress(&p, g_w1p);    w1p  = (f16*)p;
    cudaGetSymbolAddress(&p, g_w2p);    w2p  = (f16*)p;

    const int smemsz = NSTG * 2 * STG;   // 110592 B
    cudaFuncSetAttribute(gemm_f16k<2, true>,  cudaFuncAttributeMaxDynamicSharedMemorySize, smemsz);
    cudaFuncSetAttribute(gemm_f16k<1, false>, cudaFuncAttributeMaxDynamicSharedMemorySize, smemsz);

    prep_w<<<(int)(((size_t)HH * DD + 255) / 256), 256>>>(W1, W2, w1p, w2p);
    quant_x_kernel<<<MTOK, 256>>>(x, ridx, qx, xs);
    gemm_f16k<2, true><<<dim3(HH / 128, MTOK / 128), 128, smemsz>>>(
        qx, w1p, 1.0f / 2048.0f, xs, b1, hbuf, MTOK, HH, DD);
    quant_h_kernel<<<MTOK, 256>>>(hbuf, qh, hs);
    gemm_f16k<1, false><<<dim3(DD / 128, MTOK / 128), 128, smemsz>>>(
        qh, w2p, 1.0f, hs, b2, out, MTOK, DD, HH);
}

// round 15
// speedup vs baseline: 1.0151x; 1.0151x over previous
#include <cuda_runtime.h>
#include <cuda_fp16.h>
#include <math.h>
#include <stdint.h>

#define MTOK 32768
#define DD   1152
#define HH   4608
#define PREPB 20736   // (HH*DD)/256 blocks of weight-prep work

typedef __half f16;

// ---------------- scratch (static device globals; no runtime alloc) ----------------
__device__ f16   g_qx[(size_t)MTOK * DD];        // quantized x as fp16 ints (exact)
__device__ float g_xscale[MTOK];
__device__ f16   g_qh[(size_t)MTOK * HH];        // quantized h as fp16 ints (exact)
__device__ float g_hscale[MTOK];
__device__ float g_h[(size_t)MTOK * HH];         // post-GELU h (fp32)
__device__ f16   g_w1p[(size_t)2 * HH * DD];     // W1: plane0 = lo*2048, plane1 = hi
__device__ f16   g_w2p[(size_t)DD * HH];         // W2: single fp16 plane

// ---------------- helpers ----------------
__device__ __forceinline__ float gelu_exact(float v) {
    return 0.5f * v * (1.0f + erff(v * 0.70710678118654752440f));
}
__device__ __forceinline__ void cpa16(void* s, const void* g) {
    unsigned sa = (unsigned)__cvta_generic_to_shared(s);
    asm volatile("cp.async.cg.shared.global [%0], [%1], 16;\n" :: "r"(sa), "l"(g));
}
__device__ __forceinline__ void cpcommit() { asm volatile("cp.async.commit_group;\n"); }
__device__ __forceinline__ void cpwaitg1() { asm volatile("cp.async.wait_group 1;\n"); }

__device__ __forceinline__ void ldm_x4(uint32_t* r, uint32_t addr) {
    asm volatile("ldmatrix.sync.aligned.m8n8.x4.shared.b16 {%0,%1,%2,%3}, [%4];\n"
                 : "=r"(r[0]), "=r"(r[1]), "=r"(r[2]), "=r"(r[3]) : "r"(addr));
}
__device__ __forceinline__ void mma_f16(float* d, const uint32_t* a, uint32_t b0, uint32_t b1) {
    asm volatile("mma.sync.aligned.m16n8k16.row.col.f32.f16.f16.f32 "
                 "{%0,%1,%2,%3}, {%4,%5,%6,%7}, {%8,%9}, {%0,%1,%2,%3};\n"
                 : "+f"(d[0]), "+f"(d[1]), "+f"(d[2]), "+f"(d[3])
                 : "r"(a[0]), "r"(a[1]), "r"(a[2]), "r"(a[3]),
                   "r"(b0), "r"(b1));
}

// ---------------- fused prologue: weight planes + x quantization ----------------
// blocks [0, PREPB): W1 -> (lo*2048, hi) fp16 planes, W2 -> fp16 plane.
// blocks [PREPB, PREPB+MTOK): per-token fake-quant of x (with channel reorder).
// The two halves are independent; fusing overlaps prep's DRAM time under quant_x.
__global__ void prologue_kernel(const float* __restrict__ W1, const float* __restrict__ W2,
                                f16* __restrict__ w1p, f16* __restrict__ w2p,
                                const float* __restrict__ x, const int* __restrict__ ridx,
                                f16* __restrict__ qx, float* __restrict__ xs) {
    if (blockIdx.x < PREPB) {
        size_t i = (size_t)blockIdx.x * 256 + threadIdx.x;
        float w = W1[i];
        f16 hi = __float2half_rn(w);
        float lo = w - __half2float(hi);
        w1p[i]                    = __float2half_rn(lo * 2048.0f);
        w1p[(size_t)HH * DD + i]  = hi;
        w2p[i] = __float2half_rn(W2[i]);
        return;
    }
    __shared__ float sv[DD];
    __shared__ float red[9];
    int m = blockIdx.x - PREPB, tid = threadIdx.x;
    const float* row = x + (size_t)m * DD;
    float mx = 0.0f;
    for (int d = tid; d < DD; d += 256) {
        float v = row[ridx[d]];
        sv[d] = v;
        mx = fmaxf(mx, fabsf(v));
    }
    #pragma unroll
    for (int o = 16; o > 0; o >>= 1) mx = fmaxf(mx, __shfl_xor_sync(0xffffffffu, mx, o));
    if ((tid & 31) == 0) red[tid >> 5] = mx;
    __syncthreads();
    if (tid == 0) {
        float t = red[0];
        #pragma unroll
        for (int i = 1; i < 8; i++) t = fmaxf(t, red[i]);
        red[8] = fmaxf(__fdiv_rn(t, 127.0f), 1e-8f);
    }
    __syncthreads();
    float scale = red[8];
    for (int d = tid; d < DD; d += 256) {
        float q = rintf(__fdiv_rn(sv[d], scale));
        q = fminf(fmaxf(q, -128.0f), 127.0f);
        qx[(size_t)m * DD + d] = __float2half_rn(q);   // exact: |q| <= 128
    }
    if (tid == 0) xs[m] = scale;
}

// ---------------- quant of h -> fp16 ints (vectorized, single gmem pass) ----------------
__global__ void quant_h_kernel(const float* __restrict__ h, f16* __restrict__ qh,
                               float* __restrict__ hs) {
    __shared__ float red[9];
    int m = blockIdx.x, tid = threadIdx.x;
    const float4* row = (const float4*)(h + (size_t)m * HH);   // 1152 float4
    float4 v[5];
    float mx = 0.0f;
    #pragma unroll
    for (int i = 0; i < 5; i++) {
        int idx = tid + i * 256;
        if (idx < 1152) {
            v[i] = row[idx];
            mx = fmaxf(mx, fmaxf(fmaxf(fabsf(v[i].x), fabsf(v[i].y)),
                                 fmaxf(fabsf(v[i].z), fabsf(v[i].w))));
        }
    }
    #pragma unroll
    for (int o = 16; o > 0; o >>= 1) mx = fmaxf(mx, __shfl_xor_sync(0xffffffffu, mx, o));
    if ((tid & 31) == 0) red[tid >> 5] = mx;
    __syncthreads();
    if (tid == 0) {
        float t = red[0];
        #pragma unroll
        for (int i = 1; i < 8; i++) t = fmaxf(t, red[i]);
        red[8] = fmaxf(__fdiv_rn(t, 127.0f), 1e-8f);
    }
    __syncthreads();
    float scale = red[8];
    uint2* out = (uint2*)(qh + (size_t)m * HH);   // 4 halves per store
    #pragma unroll
    for (int i = 0; i < 5; i++) {
        int idx = tid + i * 256;
        if (idx < 1152) {
            float q0 = fminf(fmaxf(rintf(__fdiv_rn(v[i].x, scale)), -128.0f), 127.0f);
            float q1 = fminf(fmaxf(rintf(__fdiv_rn(v[i].y, scale)), -128.0f), 127.0f);
            float q2 = fminf(fmaxf(rintf(__fdiv_rn(v[i].z, scale)), -128.0f), 127.0f);
            float q3 = fminf(fmaxf(rintf(__fdiv_rn(v[i].w, scale)), -128.0f), 127.0f);
            __half2 lo = __floats2half2_rn(q0, q1);
            __half2 hi = __floats2half2_rn(q2, q3);
            uint2 pk;
            pk.x = *(uint32_t*)&lo;
            pk.y = *(uint32_t*)&hi;
            out[idx] = pk;
        }
    }
    if (tid == 0) hs[m] = scale;
}

// ---------------- fp16 multi-plane GEMM (mma m16n8k16, ldmatrix, 3-stage pipe) ----------------
// C = op( rs[m] * HornerFold_p(A @ Bp^T) + bias[n] ),  fold scale = psc between planes.
// CTA 128x128, 8 warps (4x2), warp tile 32x64. K-chunk = 64 halves (128B/row).
// R6-proven schedule: wait -> sync -> compute(st) -> load(st+2). Verified local
// optimum (R8 reg-pressure, R9 barrier-scope, R10 issue-order, R12 tile-aspect).
#define KC    64
#define SSTB  144
#define STG   (128 * SSTB)     // 18432 B per stage
#define NSTG  3

template<int P, bool DO_GELU>
__global__ __launch_bounds__(256, 2)
void gemm_f16k(const f16* __restrict__ A, const f16* __restrict__ Bp, float psc,
               const float* __restrict__ rs, const float* __restrict__ bias,
               float* __restrict__ C, int M, int N, int K) {
    extern __shared__ char sm[];
    char* smA = sm;
    char* smB = sm + NSTG * STG;

    const int tid  = threadIdx.x;
    const int m0   = blockIdx.y * 128;
    const int n0   = blockIdx.x * 128;
    const int lane = tid & 31, warp = tid >> 5;
    const int wm = warp >> 1, wn = warp & 1;
    const int g  = lane >> 2, t4 = lane & 3;

    float acc[2][8][4];
    #pragma unroll
    for (int mt = 0; mt < 2; mt++)
        #pragma unroll
        for (int nt = 0; nt < 8; nt++)
            #pragma unroll
            for (int i = 0; i < 4; i++) acc[mt][nt][i] = 0.0f;

    const char* Ag = (const char*)(A + (size_t)m0 * K);
    const int cpk = K / KC;
    const int nch = P * cpk;

    // per-lane LDSM byte offsets within a stage
    const int aoffs = (wm * 32 + (lane & 15)) * SSTB + ((lane >> 4) & 1) * 16;
    const int boffs = (wn * 64 + (lane & 7) + ((lane >> 4) & 1) * 8) * SSTB
                    + ((lane >> 3) & 1) * 16;

    auto load_chunk = [&](int ch, int st) {
        int p  = (P == 1) ? 0 : (ch / cpk);
        int kb = ((P == 1) ? ch : (ch % cpk)) * (KC * 2);   // byte offset along K
        const char* Ab = Ag + kb;
        const char* Bb = (const char*)(Bp + (size_t)p * N * K + (size_t)n0 * K) + kb;
        #pragma unroll
        for (int i = 0; i < 4; i++) {
            int id = tid + i * 256;           // 0..1023
            int r = id >> 3, c = (id & 7) << 4;
            cpa16(smA + st * STG + r * SSTB + c, Ab + (size_t)r * (K * 2) + c);
            cpa16(smB + st * STG + r * SSTB + c, Bb + (size_t)r * (K * 2) + c);
        }
    };

    auto compute_stage = [&](int st) {
        uint32_t Abase = (uint32_t)__cvta_generic_to_shared(smA + st * STG) + aoffs;
        uint32_t Bbase = (uint32_t)__cvta_generic_to_shared(smB + st * STG) + boffs;
        #pragma unroll
        for (int ks = 0; ks < 4; ks++) {
            uint32_t a[2][4];
            ldm_x4(a[0], Abase + ks * 32);
            ldm_x4(a[1], Abase + 16 * SSTB + ks * 32);
            uint32_t bb[4][4];
            #pragma unroll
            for (int ntp = 0; ntp < 4; ntp++)
                ldm_x4(bb[ntp], Bbase + ntp * 16 * SSTB + ks * 32);
            #pragma unroll
            for (int mt = 0; mt < 2; mt++)
                #pragma unroll
                for (int nt = 0; nt < 8; nt++)
                    mma_f16(acc[mt][nt], a[mt], bb[nt >> 1][(nt & 1) * 2],
                            bb[nt >> 1][(nt & 1) * 2 + 1]);
        }
    };

    load_chunk(0, 0); cpcommit();
    load_chunk(1, 1); cpcommit();

    for (int i = 0; i < nch; i++) {
        int st = i % 3;
        cpwaitg1();
        __syncthreads();
        compute_stage(st);
        if (P == 2 && i == cpk - 1) {           // Horner fold between planes
            #pragma unroll
            for (int mt = 0; mt < 2; mt++)
                #pragma unroll
                for (int nt = 0; nt < 8; nt++)
                    #pragma unroll
                    for (int k = 0; k < 4; k++) acc[mt][nt][k] *= psc;
        }
        int j = i + 2;
        if (j < nch) load_chunk(j, j % 3);
        cpcommit();                             // empty group at tail keeps wait semantics
    }

    // epilogue
    #pragma unroll
    for (int mt = 0; mt < 2; mt++) {
        int r0 = m0 + wm * 32 + mt * 16 + g;
        float s0 = rs[r0], s1 = rs[r0 + 8];
        #pragma unroll
        for (int nt = 0; nt < 8; nt++) {
            int c0 = n0 + wn * 64 + nt * 8 + (t4 << 1);
            float bb0 = bias[c0], bb1 = bias[c0 + 1];
            float v00 = acc[mt][nt][0] * s0 + bb0;
            float v01 = acc[mt][nt][1] * s0 + bb1;
            float v10 = acc[mt][nt][2] * s1 + bb0;
            float v11 = acc[mt][nt][3] * s1 + bb1;
            if (DO_GELU) {
                v00 = gelu_exact(v00); v01 = gelu_exact(v01);
                v10 = gelu_exact(v10); v11 = gelu_exact(v11);
            }
            *(float2*)&C[(size_t)r0 * N + c0]       = make_float2(v00, v01);
            *(float2*)&C[(size_t)(r0 + 8) * N + c0] = make_float2(v10, v11);
        }
    }
}

// ---------------- launch ----------------
extern "C" void kernel_launch(void* const* d_in, const int* in_sizes, int n_in,
                              void* d_out, int out_size) {
    const float* x    = (const float*)d_in[0];
    const int*   ridx = (const int*)  d_in[1];
    const float* W1   = (const float*)d_in[2];
    const float* b1   = (const float*)d_in[3];
    const float* W2   = (const float*)d_in[4];
    const float* b2   = (const float*)d_in[5];
    float* out = (float*)d_out;
    (void)in_sizes; (void)n_in; (void)out_size;

    void* p;
    f16 *qx, *qh, *w1p, *w2p;
    float *xs, *hs, *hbuf;
    cudaGetSymbolAddress(&p, g_qx);     qx   = (f16*)p;
    cudaGetSymbolAddress(&p, g_xscale); xs   = (float*)p;
    cudaGetSymbolAddress(&p, g_qh);     qh   = (f16*)p;
    cudaGetSymbolAddress(&p, g_hscale); hs   = (float*)p;
    cudaGetSymbolAddress(&p, g_h);      hbuf = (float*)p;
    cudaGetSymbolAddress(&p, g_w1p);    w1p  = (f16*)p;
    cudaGetSymbolAddress(&p, g_w2p);    w2p  = (f16*)p;

    const int smemsz = NSTG * 2 * STG;   // 110592 B
    cudaFuncSetAttribute(gemm_f16k<2, true>,  cudaFuncAttributeMaxDynamicSharedMemorySize, smemsz);
    cudaFuncSetAttribute(gemm_f16k<1, false>, cudaFuncAttributeMaxDynamicSharedMemorySize, smemsz);

    prologue_kernel<<<PREPB + MTOK, 256>>>(W1, W2, w1p, w2p, x, ridx, qx, xs);
    gemm_f16k<2, true><<<dim3(HH / 128, MTOK / 128), 256, smemsz>>>(
        qx, w1p, 1.0f / 2048.0f, xs, b1, hbuf, MTOK, HH, DD);
    quant_h_kernel<<<MTOK, 256>>>(hbuf, qh, hs);
    gemm_f16k<1, false><<<dim3(DD / 128, MTOK / 128), 256, smemsz>>>(
        qh, w2p, 1.0f, hs, b2, out, MTOK, DD, HH);
}